// round 4
// baseline (speedup 1.0000x reference)
#include <cuda_runtime.h>

#define CIN    64
#define COUT   64
#define NPTS   2048
#define NBATCH 16
#define BNT    (NBATCH*NPTS)   /* 32768 */
#define KN     20
#define KSN    20
#define PT     16              /* points per block */
#define COLS   (PT*KN)         /* 320 */
#define SM_FLOATS (CIN*COLS + CIN*COUT + CIN*COUT + PT*KN*KSN + COUT*17)

// ---------------- scratch (static device memory; no allocations) ----------------
__device__ float  g_flatT[(size_t)BNT * CIN];     // 8 MB: point-major features
__device__ float  g_outpre[(size_t)BNT * COUT];   // 8 MB: pre-BN output, (b,o,n) layout
__device__ float  g_Wbt[CIN * COUT];              // transposed wb: [c][o]
__device__ float  g_Wct[CIN * COUT];              // transposed (wa-wb): [c][o]
__device__ double g_sum[COUT];
__device__ double g_sumsq[COUT];
__device__ float  g_scale[COUT];
__device__ float  g_shift[COUT];

// ---------------- kernel 0: transpose feature (b,c,n) -> flat (b*n, c) ----------
__global__ void k_transpose(const float* __restrict__ feat) {
    __shared__ float tile[32][33];
    int b  = blockIdx.z;
    int c0 = blockIdx.x * 32;
    int n0 = blockIdx.y * 32;
    int tx = threadIdx.x, ty = threadIdx.y;   // 32 x 8
#pragma unroll
    for (int i = 0; i < 4; i++)
        tile[ty + i*8][tx] = feat[((size_t)b*CIN + c0 + ty + i*8)*NPTS + n0 + tx];
    __syncthreads();
#pragma unroll
    for (int i = 0; i < 4; i++)
        g_flatT[((size_t)b*NPTS + n0 + ty + i*8)*CIN + c0 + tx] = tile[tx][ty + i*8];
}

// ---------------- kernel 1: fold permute into weights; zero BN stats ------------
__global__ void k_prep(const float* __restrict__ conv_w) {
    int t = threadIdx.x;   // 256 threads
    if (t < COUT) { g_sum[t] = 0.0; g_sumsq[t] = 0.0; }
    for (int i = t; i < CIN*COUT; i += 256) {
        int o = i / CIN, c = i % CIN;
        // post-permute index p(c) = (c%32)*4 + c/32 ; diff block lives at old-ch c+64
        float wa = conv_w[o*128 + (c & 31)*4 + (c >> 5)];
        float wb = conv_w[o*128 + (c & 31)*4 + 2 + (c >> 5)];
        g_Wbt[c*COUT + o] = wb;
        g_Wct[c*COUT + o] = wa - wb;
    }
}

// ---------------- kernel 2: main fused gather+GEMM+mix+max ----------------------
__global__ void __launch_bounds__(256, 1)
k_main(const int* __restrict__ nidx,          // int32: JAX x64-disabled downcasts int64
       const float* __restrict__ perm,
       const float* __restrict__ conv_b)
{
    extern __shared__ float sm[];
    float* Xs  = sm;                       // [64][320]  gathered neighbor features
    float* Wbs = Xs  + CIN*COLS;           // [64][64]   wb^T
    float* Wcs = Wbs + CIN*COUT;           // [64][64]   (wa-wb)^T
    float* Ps  = Wcs + CIN*COUT;           // [16][20s][20k] transposed permatrix
    float* Os  = Ps  + PT*KN*KSN;          // [64][17]   per-block outputs (padded)

    const int t  = threadIdx.x;
    const int n0 = blockIdx.x * PT;

    // stage weights
    for (int i = t; i < CIN*COUT; i += 256) { Wbs[i] = g_Wbt[i]; Wcs[i] = g_Wct[i]; }
    // stage P, transposed to [s][k] for contiguous float4 reads
    for (int i = t; i < PT*KN*KSN; i += 256) {
        int pt = i / 400, r = i % 400;
        int k = r / 20, s = r % 20;
        Ps[pt*400 + s*20 + k] = perm[(size_t)(n0 + pt)*400 + r];
    }
    // gather neighbor feature columns
    for (int col = t; col < COLS; col += 256) {
        int pt = col / KN, k = col % KN;
        int idx = nidx[(n0 + pt)*KN + k] & (BNT - 1);   // clamp: identity for valid input
        const float4* src = (const float4*)(g_flatT + (size_t)idx * CIN);
#pragma unroll
        for (int c4 = 0; c4 < 16; c4++) {
            float4 v = src[c4];
            Xs[(c4*4 + 0)*COLS + col] = v.x;
            Xs[(c4*4 + 1)*COLS + col] = v.y;
            Xs[(c4*4 + 2)*COLS + col] = v.z;
            Xs[(c4*4 + 3)*COLS + col] = v.w;
        }
    }
    __syncthreads();

    const int og = t & 15;    // output-channel group: o = og*4 .. og*4+3
    const int pt = t >> 4;    // point within block

    float acc[4][KN];
    float a2[4] = {0.f, 0.f, 0.f, 0.f};
#pragma unroll
    for (int i = 0; i < 4; i++)
#pragma unroll
        for (int k = 0; k < KN; k++) acc[i][k] = 0.f;

    const float* xrow = Xs + pt*KN;
#pragma unroll 4
    for (int c = 0; c < CIN; c++) {
        float4 w  = *(const float4*)(Wbs + c*COUT + og*4);
        float4 wc = *(const float4*)(Wcs + c*COUT + og*4);
        float x[KN];
#pragma unroll
        for (int q = 0; q < 5; q++) {
            float4 v = *(const float4*)(xrow + c*COLS + q*4);
            x[q*4+0] = v.x; x[q*4+1] = v.y; x[q*4+2] = v.z; x[q*4+3] = v.w;
        }
        a2[0] += wc.x * x[0]; a2[1] += wc.y * x[0];
        a2[2] += wc.z * x[0]; a2[3] += wc.w * x[0];
#pragma unroll
        for (int k = 0; k < KN; k++) {
            acc[0][k] += w.x * x[k];
            acc[1][k] += w.y * x[k];
            acc[2][k] += w.z * x[k];
            acc[3][k] += w.w * x[k];
        }
    }
#pragma unroll
    for (int i = 0; i < 4; i++)
#pragma unroll
        for (int k = 0; k < KN; k++) acc[i][k] += a2[i];

    float bias[4], m[4];
#pragma unroll
    for (int i = 0; i < 4; i++) { bias[i] = __ldg(conv_b + og*4 + i); m[i] = -3.4e38f; }

    const float* prow = Ps + pt*400;
#pragma unroll 2
    for (int s = 0; s < KSN; s++) {
        float p[KN];
#pragma unroll
        for (int q = 0; q < 5; q++) {
            float4 v = *(const float4*)(prow + s*20 + q*4);
            p[q*4+0] = v.x; p[q*4+1] = v.y; p[q*4+2] = v.z; p[q*4+3] = v.w;
        }
        float v0 = bias[0], v1 = bias[1], v2 = bias[2], v3 = bias[3];
#pragma unroll
        for (int k = 0; k < KN; k++) {
            v0 += p[k]*acc[0][k]; v1 += p[k]*acc[1][k];
            v2 += p[k]*acc[2][k]; v3 += p[k]*acc[3][k];
        }
        m[0] = fmaxf(m[0], v0); m[1] = fmaxf(m[1], v1);
        m[2] = fmaxf(m[2], v2); m[3] = fmaxf(m[3], v3);
    }
#pragma unroll
    for (int i = 0; i < 4; i++) Os[(og*4 + i)*17 + pt] = m[i];
    __syncthreads();

    // BN partial sums (per channel, over this block's 16 points)
    if (t < COUT) {
        float s1 = 0.f, s2 = 0.f;
#pragma unroll
        for (int q = 0; q < PT; q++) { float v = Os[t*17 + q]; s1 += v; s2 += v*v; }
        atomicAdd(&g_sum[t],   (double)s1);
        atomicAdd(&g_sumsq[t], (double)s2);
    }
    // write pre-BN output directly in (b, o, n) layout, coalesced float4
    {
        int o  = t >> 2;
        int i0 = (t & 3) * 4;
        int b  = n0 / NPTS, nn = n0 % NPTS;
        float4 v = make_float4(Os[o*17 + i0], Os[o*17 + i0 + 1],
                               Os[o*17 + i0 + 2], Os[o*17 + i0 + 3]);
        *(float4*)(g_outpre + ((size_t)(b*COUT + o))*NPTS + nn + i0) = v;
    }
}

// ---------------- kernel 3: finalize BN stats -----------------------------------
__global__ void k_finalize(const float* __restrict__ bn_w, const float* __restrict__ bn_b) {
    int o = threadIdx.x;   // 64
    double mean = g_sum[o]   * (1.0 / (double)BNT);
    double var  = g_sumsq[o] * (1.0 / (double)BNT) - mean*mean;
    float istd  = rsqrtf((float)var + 1e-5f);
    g_scale[o] = bn_w[o] * istd;
    g_shift[o] = bn_b[o] - (float)mean * istd * bn_w[o];
}

// ---------------- kernel 4: apply BN --------------------------------------------
__global__ void k_norm(float* __restrict__ out) {
    int i4 = blockIdx.x * 256 + threadIdx.x;     // 524288 float4s
    int o  = (i4 >> 9) & 63;
    float4 v = *(const float4*)(g_outpre + (size_t)i4 * 4);
    float sc = g_scale[o], sh = g_shift[o];
    v.x = v.x*sc + sh; v.y = v.y*sc + sh; v.z = v.z*sc + sh; v.w = v.w*sc + sh;
    ((float4*)out)[i4] = v;
}

// ---------------- launch --------------------------------------------------------
extern "C" void kernel_launch(void* const* d_in, const int* in_sizes, int n_in,
                              void* d_out, int out_size)
{
    const float* feature = (const float*)d_in[0];
    const int*   nidx    = (const int*)d_in[1];     // int32 (JAX x64 disabled)
    const float* perm    = (const float*)d_in[2];
    const float* conv_w  = (const float*)d_in[3];
    const float* conv_b  = (const float*)d_in[4];
    const float* bn_w    = (const float*)d_in[5];
    const float* bn_b    = (const float*)d_in[6];
    float*       out     = (float*)d_out;

    size_t smem = SM_FLOATS * sizeof(float);   // ~141.25 KB
    cudaFuncSetAttribute(k_main, cudaFuncAttributeMaxDynamicSharedMemorySize, (int)smem);

    k_transpose<<<dim3(2, 64, 16), dim3(32, 8)>>>(feature);
    k_prep<<<1, 256>>>(conv_w);
    k_main<<<BNT/PT, 256, smem>>>(nidx, perm, conv_b);
    k_finalize<<<1, 64>>>(bn_w, bn_b);
    k_norm<<<(BNT*COUT)/(256*4), 256>>>(out);
}

// round 5
// speedup vs baseline: 1.0040x; 1.0040x over previous
#include <cuda_runtime.h>

#define CIN    64
#define COUT   64
#define NPTS   2048
#define NBATCH 16
#define BNT    (NBATCH*NPTS)   /* 32768 */
#define KN     20
#define KSN    20
#define PT     16              /* points per block */
#define COLS   (PT*KN)         /* 320 */
#define SM_FLOATS (CIN*COLS + CIN*COUT + CIN*COUT + PT*KN*KSN + COUT*17)

typedef unsigned long long ull;

// packed f32x2 helpers (sm_100a FFMA2 path — only reachable via PTX)
#define FMA2(dc, a, b) \
    asm("fma.rn.f32x2 %0, %1, %2, %0;" : "+l"(dc) : "l"(a), "l"(b))
#define ADD2(dc, a) \
    asm("add.rn.f32x2 %0, %0, %1;" : "+l"(dc) : "l"(a))
#define PACK2(d, s) \
    asm("mov.b64 %0, {%1, %1};" : "=l"(d) : "r"(__float_as_uint(s)))
#define UNPACK2(lo, hi, v) do { unsigned _a, _b; \
    asm("mov.b64 {%0, %1}, %2;" : "=r"(_a), "=r"(_b) : "l"(v)); \
    lo = __uint_as_float(_a); hi = __uint_as_float(_b); } while (0)

// ---------------- scratch (static device memory; no allocations) ----------------
__device__ float  g_flatT[(size_t)BNT * CIN];     // 8 MB: point-major features
__device__ float  g_outpre[(size_t)BNT * COUT];   // 8 MB: pre-BN output, (b,o,n) layout
__device__ float  g_Wbt[CIN * COUT];              // transposed wb: [c][o]
__device__ float  g_Wct[CIN * COUT];              // transposed (wa-wb): [c][o]
__device__ double g_sum[COUT];
__device__ double g_sumsq[COUT];

// ------- kernel 0: transpose feature (b,c,n) -> flat (b*n, c); block 0 also preps weights
__global__ void k_transpose(const float* __restrict__ feat, const float* __restrict__ conv_w) {
    __shared__ float tile[32][33];
    int b  = blockIdx.z;
    int c0 = blockIdx.x * 32;
    int n0 = blockIdx.y * 32;
    int tx = threadIdx.x, ty = threadIdx.y;   // 32 x 8

    if (blockIdx.x == 0 && blockIdx.y == 0 && blockIdx.z == 0) {
        int t = ty * 32 + tx;   // 0..255
        if (t < COUT) { g_sum[t] = 0.0; g_sumsq[t] = 0.0; }
        for (int i = t; i < CIN*COUT; i += 256) {
            int o = i / CIN, c = i % CIN;
            // post-permute index p(c) = (c%32)*4 + c/32 ; diff block at old-ch c+64
            float wa = conv_w[o*128 + (c & 31)*4 + (c >> 5)];
            float wb = conv_w[o*128 + (c & 31)*4 + 2 + (c >> 5)];
            g_Wbt[c*COUT + o] = wb;
            g_Wct[c*COUT + o] = wa - wb;
        }
    }

#pragma unroll
    for (int i = 0; i < 4; i++)
        tile[ty + i*8][tx] = feat[((size_t)b*CIN + c0 + ty + i*8)*NPTS + n0 + tx];
    __syncthreads();
#pragma unroll
    for (int i = 0; i < 4; i++)
        g_flatT[((size_t)b*NPTS + n0 + ty + i*8)*CIN + c0 + tx] = tile[tx][ty + i*8];
}

// ---------------- kernel 1: main fused gather+GEMM+mix+max ----------------------
__global__ void __launch_bounds__(256, 1)
k_main(const int* __restrict__ nidx,          // int32 (JAX x64 disabled)
       const float* __restrict__ perm,
       const float* __restrict__ conv_b)
{
    extern __shared__ float sm[];
    float* Xs  = sm;                       // [64][320]  gathered neighbor features
    float* Wbs = Xs  + CIN*COLS;           // [64][64]   wb^T
    float* Wcs = Wbs + CIN*COUT;           // [64][64]   (wa-wb)^T
    float* Ps  = Wcs + CIN*COUT;           // [16][20s][20k] transposed permatrix
    float* Os  = Ps  + PT*KN*KSN;          // [64][17]   per-block outputs (padded)

    const int t  = threadIdx.x;
    const int n0 = blockIdx.x * PT;

    for (int i = t; i < CIN*COUT; i += 256) { Wbs[i] = g_Wbt[i]; Wcs[i] = g_Wct[i]; }
    for (int i = t; i < PT*KN*KSN; i += 256) {
        int pt = i / 400, r = i % 400;
        int k = r / 20, s = r % 20;
        Ps[pt*400 + s*20 + k] = perm[(size_t)(n0 + pt)*400 + r];
    }
    for (int col = t; col < COLS; col += 256) {
        int pt = col / KN, k = col % KN;
        int idx = nidx[(n0 + pt)*KN + k] & (BNT - 1);   // identity for valid input
        const float4* src = (const float4*)(g_flatT + (size_t)idx * CIN);
#pragma unroll
        for (int c4 = 0; c4 < 16; c4++) {
            float4 v = src[c4];
            Xs[(c4*4 + 0)*COLS + col] = v.x;
            Xs[(c4*4 + 1)*COLS + col] = v.y;
            Xs[(c4*4 + 2)*COLS + col] = v.z;
            Xs[(c4*4 + 3)*COLS + col] = v.w;
        }
    }
    __syncthreads();

    const int og = t & 15;    // output-channel group: o = og*4 .. og*4+3
    const int pt = t >> 4;    // point within block

    // ---- stage 1: C1[o,k] = sum_c wb[o,c] x[c,k]  (+ a2[o] = sum_c wc[o,c] x[c,0])
    ull acc2[4][10];          // f32x2 pairs over k
#pragma unroll
    for (int i = 0; i < 4; i++)
#pragma unroll
        for (int q = 0; q < 10; q++) acc2[i][q] = 0ULL;
    float a2_[4] = {0.f, 0.f, 0.f, 0.f};

    const float* xrow = Xs + pt*KN;
#pragma unroll 2
    for (int c = 0; c < CIN; c++) {
        float4 w  = *(const float4*)(Wbs + c*COUT + og*4);
        float4 wc = *(const float4*)(Wcs + c*COUT + og*4);
        ull wp0, wp1, wp2, wp3;
        PACK2(wp0, w.x); PACK2(wp1, w.y); PACK2(wp2, w.z); PACK2(wp3, w.w);

        ull x2[10];
#pragma unroll
        for (int q = 0; q < 5; q++) {
            ulonglong2 xv = *(const ulonglong2*)(xrow + c*COLS + q*4);
            x2[2*q] = xv.x; x2[2*q+1] = xv.y;
        }
        float x0 = xrow[c*COLS];
        a2_[0] = fmaf(wc.x, x0, a2_[0]);
        a2_[1] = fmaf(wc.y, x0, a2_[1]);
        a2_[2] = fmaf(wc.z, x0, a2_[2]);
        a2_[3] = fmaf(wc.w, x0, a2_[3]);

#pragma unroll
        for (int q = 0; q < 10; q++) {
            FMA2(acc2[0][q], wp0, x2[q]);
            FMA2(acc2[1][q], wp1, x2[q]);
            FMA2(acc2[2][q], wp2, x2[q]);
            FMA2(acc2[3][q], wp3, x2[q]);
        }
    }
    {
        ull a2p[4];
#pragma unroll
        for (int i = 0; i < 4; i++) PACK2(a2p[i], a2_[i]);
#pragma unroll
        for (int i = 0; i < 4; i++)
#pragma unroll
            for (int q = 0; q < 10; q++) ADD2(acc2[i][q], a2p[i]);
    }

    // ---- stage 2: out[o] = bias[o] + max_s sum_k P[s,k] C1[o,k]
    float m[4] = {-3.4e38f, -3.4e38f, -3.4e38f, -3.4e38f};
    const float* prow = Ps + pt*400;
#pragma unroll 2
    for (int s = 0; s < KSN; s++) {
        ull p2[10];
#pragma unroll
        for (int q = 0; q < 5; q++) {
            ulonglong2 pv = *(const ulonglong2*)(prow + s*20 + q*4);
            p2[2*q] = pv.x; p2[2*q+1] = pv.y;
        }
        ull v0 = 0ULL, v1 = 0ULL, v2 = 0ULL, v3 = 0ULL;
#pragma unroll
        for (int q = 0; q < 10; q++) {
            FMA2(v0, p2[q], acc2[0][q]);
            FMA2(v1, p2[q], acc2[1][q]);
            FMA2(v2, p2[q], acc2[2][q]);
            FMA2(v3, p2[q], acc2[3][q]);
        }
        float lo, hi;
        UNPACK2(lo, hi, v0); m[0] = fmaxf(m[0], lo + hi);
        UNPACK2(lo, hi, v1); m[1] = fmaxf(m[1], lo + hi);
        UNPACK2(lo, hi, v2); m[2] = fmaxf(m[2], lo + hi);
        UNPACK2(lo, hi, v3); m[3] = fmaxf(m[3], lo + hi);
    }
#pragma unroll
    for (int i = 0; i < 4; i++) m[i] += __ldg(conv_b + og*4 + i);

#pragma unroll
    for (int i = 0; i < 4; i++) Os[(og*4 + i)*17 + pt] = m[i];
    __syncthreads();

    if (t < COUT) {
        float s1 = 0.f, s2 = 0.f;
#pragma unroll
        for (int q = 0; q < PT; q++) { float v = Os[t*17 + q]; s1 += v; s2 += v*v; }
        atomicAdd(&g_sum[t],   (double)s1);
        atomicAdd(&g_sumsq[t], (double)s2);
    }
    {
        int o  = t >> 2;
        int i0 = (t & 3) * 4;
        int b  = n0 / NPTS, nn = n0 % NPTS;
        float4 v = make_float4(Os[o*17 + i0], Os[o*17 + i0 + 1],
                               Os[o*17 + i0 + 2], Os[o*17 + i0 + 3]);
        *(float4*)(g_outpre + ((size_t)(b*COUT + o))*NPTS + nn + i0) = v;
    }
}

// ---------------- kernel 2: finalize BN stats + apply --------------------------
__global__ void k_norm(const float* __restrict__ bn_w, const float* __restrict__ bn_b,
                       float* __restrict__ out) {
    __shared__ float s_scale[COUT], s_shift[COUT];
    int t = threadIdx.x;
    if (t < COUT) {
        double mean = g_sum[t]   * (1.0 / (double)BNT);
        double var  = g_sumsq[t] * (1.0 / (double)BNT) - mean*mean;
        float istd  = rsqrtf((float)var + 1e-5f);
        float w     = bn_w[t];
        s_scale[t] = w * istd;
        s_shift[t] = bn_b[t] - (float)mean * istd * w;
    }
    __syncthreads();
    int i4 = blockIdx.x * 256 + t;               // 524288 float4s
    int o  = (i4 >> 9) & 63;
    float4 v = *(const float4*)(g_outpre + (size_t)i4 * 4);
    float sc = s_scale[o], sh = s_shift[o];
    v.x = v.x*sc + sh; v.y = v.y*sc + sh; v.z = v.z*sc + sh; v.w = v.w*sc + sh;
    ((float4*)out)[i4] = v;
}

// ---------------- launch --------------------------------------------------------
extern "C" void kernel_launch(void* const* d_in, const int* in_sizes, int n_in,
                              void* d_out, int out_size)
{
    const float* feature = (const float*)d_in[0];
    const int*   nidx    = (const int*)d_in[1];     // int32 (JAX x64 disabled)
    const float* perm    = (const float*)d_in[2];
    const float* conv_w  = (const float*)d_in[3];
    const float* conv_b  = (const float*)d_in[4];
    const float* bn_w    = (const float*)d_in[5];
    const float* bn_b    = (const float*)d_in[6];
    float*       out     = (float*)d_out;

    size_t smem = SM_FLOATS * sizeof(float);   // ~141.25 KB
    cudaFuncSetAttribute(k_main, cudaFuncAttributeMaxDynamicSharedMemorySize, (int)smem);

    k_transpose<<<dim3(2, 64, 16), dim3(32, 8)>>>(feature, conv_w);
    k_main<<<BNT/PT, 256, smem>>>(nidx, perm, conv_b);
    k_norm<<<(BNT*COUT)/(256*4), 256>>>(bn_w, bn_b, out);
}

// round 7
// speedup vs baseline: 2.2882x; 2.2791x over previous
#include <cuda_runtime.h>

#define CIN    64
#define COUT   64
#define NPTS   2048
#define NBATCH 16
#define BNT    (NBATCH*NPTS)   /* 32768 */
#define KN     20
#define KSN    20
#define PT     16              /* points per block in k_main */

// ---------------- scratch (static device memory; no allocations) ----------------
__device__ float  g_Y[(size_t)BNT * COUT];        // 8 MB: Y[n][o] = sum_c wb[o,c] x_n[c]
__device__ float  g_Z[(size_t)BNT * COUT];        // 8 MB: Z[n][o] = sum_c (wa-wb)[o,c] x_n[c]
__device__ float  g_outpre[(size_t)BNT * COUT];   // 8 MB: pre-BN output, (b,o,n) layout
__device__ double g_sum[COUT];
__device__ double g_sumsq[COUT];

// ------- kernel A: per-point GEMM  feature -> Y,Z  (folds the channel permute) --
__global__ void __launch_bounds__(256)
k_feat(const float* __restrict__ feat, const float* __restrict__ conv_w)
{
    __shared__ float tile[CIN * 32];   // [c][j] 32 points
    __shared__ float Wb[COUT * CIN];   // [o][c]
    __shared__ float Wc[COUT * CIN];   // [o][c]

    const int t  = threadIdx.x;          // 256
    const int ng = blockIdx.x * 32;      // global point base (32 pts, same batch)
    const int b  = ng >> 11, nn = ng & (NPTS - 1);

    if (blockIdx.x == 0 && t < COUT) { g_sum[t] = 0.0; g_sumsq[t] = 0.0; }

    // fold permute into weights (redundant per block; conv_w is L2-resident)
    for (int i = t; i < COUT*CIN; i += 256) {
        int o = i >> 6, c = i & 63;
        float wa = conv_w[o*128 + (c & 31)*4 + (c >> 5)];
        float wb = conv_w[o*128 + (c & 31)*4 + 2 + (c >> 5)];
        Wb[o*CIN + c] = wb;
        Wc[o*CIN + c] = wa - wb;
    }
    // load 64ch x 32pt feature tile, coalesced
    for (int i = t; i < CIN*32; i += 256) {
        int c = i >> 5, j = i & 31;
        tile[c*32 + j] = feat[((size_t)(b*CIN + c))*NPTS + nn + j];
    }
    __syncthreads();

    const int j  = t & 31;            // point within tile (lane id -> conflict-free)
    const int o0 = (t >> 5) * 8;      // o-octet (warp-uniform -> broadcast W reads)

    float x[CIN];
#pragma unroll
    for (int c = 0; c < CIN; c++) x[c] = tile[c*32 + j];

    float* yrow = g_Y + (size_t)(ng + j)*COUT + o0;
    float* zrow = g_Z + (size_t)(ng + j)*COUT + o0;

#pragma unroll
    for (int half = 0; half < 2; half++) {
        const float* W = half ? Wc : Wb;
        float acc[8];
#pragma unroll
        for (int oo = 0; oo < 8; oo++) {
            const float* wr = W + (o0 + oo)*CIN;
            float a = 0.f;
#pragma unroll
            for (int c = 0; c < CIN; c += 4) {
                float4 w4 = *(const float4*)(wr + c);
                a = fmaf(w4.x, x[c],   a);
                a = fmaf(w4.y, x[c+1], a);
                a = fmaf(w4.z, x[c+2], a);
                a = fmaf(w4.w, x[c+3], a);
            }
            acc[oo] = a;
        }
        float* dst = half ? zrow : yrow;
        *(float4*)(dst)     = make_float4(acc[0], acc[1], acc[2], acc[3]);
        *(float4*)(dst + 4) = make_float4(acc[4], acc[5], acc[6], acc[7]);
    }
}

// ------- kernel B: gather Y/Z + P-mix + max + BN partials -----------------------
__global__ void __launch_bounds__(256)
k_main(const int* __restrict__ nidx,          // int32 (JAX x64 disabled)
       const float* __restrict__ perm,
       const float* __restrict__ conv_b)
{
    __shared__ float Ps[PT * KN * KSN];   // [pt][s][k] transposed permatrix
    __shared__ float Os[COUT * 17];       // per-block outputs (padded)

    const int t  = threadIdx.x;
    const int n0 = blockIdx.x * PT;

    // stage P transposed to [s][k] for contiguous float4 reads
    for (int i = t; i < PT*KN*KSN; i += 256) {
        int pt = i / 400, r = i % 400;
        int k = r / 20, s = r % 20;
        Ps[pt*400 + s*20 + k] = perm[(size_t)(n0 + pt)*400 + r];
    }
    __syncthreads();

    const int og = t & 15;    // o-quad: o = og*4 .. og*4+3
    const int pt = t >> 4;    // point within block

    const int* nrow = nidx + (n0 + pt)*KN;

    // gather: lanes 0-15 read one full 256B Y row, lanes 16-31 another -> coalesced
    int idx0 = nrow[0] & (BNT - 1);
    float4 Zc = *(const float4*)(g_Z + (size_t)idx0*COUT + og*4);

    float4 Yc[KN];
#pragma unroll
    for (int k = 0; k < KN; k++) {
        int idx = nrow[k] & (BNT - 1);    // identity for valid input
        Yc[k] = *(const float4*)(g_Y + (size_t)idx*COUT + og*4);
    }
    // fold the f0-diff term: C1[.,k] = Y[nidx[k]] + Z[nidx[0]]
#pragma unroll
    for (int k = 0; k < KN; k++) {
        Yc[k].x += Zc.x; Yc[k].y += Zc.y; Yc[k].z += Zc.z; Yc[k].w += Zc.w;
    }

    float m0 = -3.4e38f, m1 = -3.4e38f, m2 = -3.4e38f, m3 = -3.4e38f;
    const float* prow = Ps + pt*400;
#pragma unroll 2
    for (int s = 0; s < KSN; s++) {
        float p[KN];
#pragma unroll
        for (int q = 0; q < 5; q++) {
            float4 v = *(const float4*)(prow + s*20 + q*4);
            p[q*4+0] = v.x; p[q*4+1] = v.y; p[q*4+2] = v.z; p[q*4+3] = v.w;
        }
        float v0 = 0.f, v1 = 0.f, v2 = 0.f, v3 = 0.f;
#pragma unroll
        for (int k = 0; k < KN; k++) {
            v0 = fmaf(p[k], Yc[k].x, v0);
            v1 = fmaf(p[k], Yc[k].y, v1);
            v2 = fmaf(p[k], Yc[k].z, v2);
            v3 = fmaf(p[k], Yc[k].w, v3);
        }
        m0 = fmaxf(m0, v0); m1 = fmaxf(m1, v1);
        m2 = fmaxf(m2, v2); m3 = fmaxf(m3, v3);
    }
    m0 += __ldg(conv_b + og*4 + 0);
    m1 += __ldg(conv_b + og*4 + 1);
    m2 += __ldg(conv_b + og*4 + 2);
    m3 += __ldg(conv_b + og*4 + 3);

    Os[(og*4 + 0)*17 + pt] = m0;
    Os[(og*4 + 1)*17 + pt] = m1;
    Os[(og*4 + 2)*17 + pt] = m2;
    Os[(og*4 + 3)*17 + pt] = m3;
    __syncthreads();

    // BN partial sums (per channel, over this block's 16 points)
    if (t < COUT) {
        float s1 = 0.f, s2 = 0.f;
#pragma unroll
        for (int q = 0; q < PT; q++) { float v = Os[t*17 + q]; s1 += v; s2 += v*v; }
        atomicAdd(&g_sum[t],   (double)s1);
        atomicAdd(&g_sumsq[t], (double)s2);
    }
    // write pre-BN output in (b, o, n) layout, coalesced float4
    {
        int o  = t >> 2;
        int i0 = (t & 3) * 4;
        int b  = n0 / NPTS, nn = n0 % NPTS;
        float4 v = make_float4(Os[o*17 + i0], Os[o*17 + i0 + 1],
                               Os[o*17 + i0 + 2], Os[o*17 + i0 + 3]);
        *(float4*)(g_outpre + ((size_t)(b*COUT + o))*NPTS + nn + i0) = v;
    }
}

// ---------------- kernel C: finalize BN stats + apply ---------------------------
__global__ void k_norm(const float* __restrict__ bn_w, const float* __restrict__ bn_b,
                       float* __restrict__ out) {
    __shared__ float s_scale[COUT], s_shift[COUT];
    int t = threadIdx.x;
    if (t < COUT) {
        double mean = g_sum[t]   * (1.0 / (double)BNT);
        double var  = g_sumsq[t] * (1.0 / (double)BNT) - mean*mean;
        float istd  = rsqrtf((float)var + 1e-5f);
        float w     = bn_w[t];
        s_scale[t] = w * istd;
        s_shift[t] = bn_b[t] - (float)mean * istd * w;
    }
    __syncthreads();
    int i4 = blockIdx.x * 256 + t;               // 524288 float4s
    int o  = (i4 >> 9) & 63;
    float4 v = *(const float4*)(g_outpre + (size_t)i4 * 4);
    float sc = s_scale[o], sh = s_shift[o];
    v.x = v.x*sc + sh; v.y = v.y*sc + sh; v.z = v.z*sc + sh; v.w = v.w*sc + sh;
    ((float4*)out)[i4] = v;
}

// ---------------- launch --------------------------------------------------------
extern "C" void kernel_launch(void* const* d_in, const int* in_sizes, int n_in,
                              void* d_out, int out_size)
{
    const float* feature = (const float*)d_in[0];
    const int*   nidx    = (const int*)d_in[1];     // int32 (JAX x64 disabled)
    const float* perm    = (const float*)d_in[2];
    const float* conv_w  = (const float*)d_in[3];
    const float* conv_b  = (const float*)d_in[4];
    const float* bn_w    = (const float*)d_in[5];
    const float* bn_b    = (const float*)d_in[6];
    float*       out     = (float*)d_out;

    k_feat<<<BNT/32, 256>>>(feature, conv_w);
    k_main<<<BNT/PT, 256>>>(nidx, perm, conv_b);
    k_norm<<<(BNT*COUT)/(256*4), 256>>>(bn_w, bn_b, out);
}

// round 9
// speedup vs baseline: 2.3126x; 1.0107x over previous
#include <cuda_runtime.h>

#define CIN    64
#define COUT   64
#define NPTS   2048
#define NBATCH 16
#define BNT    (NBATCH*NPTS)   /* 32768 */
#define KN     20
#define KSN    20
#define PT     16              /* points per block in k_main */
#define NREP   8               /* replicated BN-stat bins */

// ---------------- scratch (static device memory; no allocations) ----------------
__device__ float  g_Y[(size_t)BNT * COUT];        // 8 MB: Y[n][o] = sum_c wb[o,c] x_n[c]
__device__ float  g_Z[(size_t)BNT * COUT];        // 8 MB: Z[n][o] = sum_c (wa-wb)[o,c] x_n[c]
__device__ float  g_outpre[(size_t)BNT * COUT];   // 8 MB: pre-BN output, (b,o,n) layout
__device__ float  g_sumf[NREP][COUT];
__device__ float  g_sumsqf[NREP][COUT];

// ------- kernel 0: zero replicated BN-stat bins (also shifts ncu capture slot) --
__global__ void k_init() {
    int t = threadIdx.x;                 // 512
    if (t < NREP*COUT)  ((float*)g_sumf)[t]   = 0.f;
    else                ((float*)g_sumsqf)[t - NREP*COUT] = 0.f;
}

// ------- kernel A: per-point GEMM  feature -> Y,Z  (folds the channel permute) --
__global__ void __launch_bounds__(256)
k_feat(const float* __restrict__ feat, const float* __restrict__ conv_w)
{
    __shared__ float tile[CIN * 32];   // [c][j] 32 points
    __shared__ float Wb[COUT * CIN];   // [o][c]
    __shared__ float Wc[COUT * CIN];   // [o][c]

    const int t  = threadIdx.x;          // 256
    const int ng = blockIdx.x * 32;      // global point base (32 pts, same batch)
    const int b  = ng >> 11, nn = ng & (NPTS - 1);

    // fold permute into weights (redundant per block; conv_w is L2-resident)
    for (int i = t; i < COUT*CIN; i += 256) {
        int o = i >> 6, c = i & 63;
        float wa = conv_w[o*128 + (c & 31)*4 + (c >> 5)];
        float wb = conv_w[o*128 + (c & 31)*4 + 2 + (c >> 5)];
        Wb[o*CIN + c] = wb;
        Wc[o*CIN + c] = wa - wb;
    }
    // load 64ch x 32pt feature tile, coalesced
    for (int i = t; i < CIN*32; i += 256) {
        int c = i >> 5, j = i & 31;
        tile[c*32 + j] = feat[((size_t)(b*CIN + c))*NPTS + nn + j];
    }
    __syncthreads();

    const int j  = t & 31;            // point within tile (lane id -> conflict-free)
    const int o0 = (t >> 5) * 8;      // o-octet (warp-uniform -> broadcast W reads)

    float x[CIN];
#pragma unroll
    for (int c = 0; c < CIN; c++) x[c] = tile[c*32 + j];

    float* yrow = g_Y + (size_t)(ng + j)*COUT + o0;
    float* zrow = g_Z + (size_t)(ng + j)*COUT + o0;

#pragma unroll
    for (int half = 0; half < 2; half++) {
        const float* W = half ? Wc : Wb;
        float acc[8];
#pragma unroll
        for (int oo = 0; oo < 8; oo++) {
            const float* wr = W + (o0 + oo)*CIN;
            float a = 0.f;
#pragma unroll
            for (int c = 0; c < CIN; c += 4) {
                float4 w4 = *(const float4*)(wr + c);
                a = fmaf(w4.x, x[c],   a);
                a = fmaf(w4.y, x[c+1], a);
                a = fmaf(w4.z, x[c+2], a);
                a = fmaf(w4.w, x[c+3], a);
            }
            acc[oo] = a;
        }
        float* dst = half ? zrow : yrow;
        *(float4*)(dst)     = make_float4(acc[0], acc[1], acc[2], acc[3]);
        *(float4*)(dst + 4) = make_float4(acc[4], acc[5], acc[6], acc[7]);
    }
}

// ------- kernel B: gather Y/Z + P-mix + max + BN partials -----------------------
__global__ void __launch_bounds__(256)
k_main(const int* __restrict__ nidx,          // int32 (JAX x64 disabled)
       const float* __restrict__ perm,
       const float* __restrict__ conv_b)
{
    __shared__ float Ps[PT * KN * KSN];   // [pt][s][k] transposed permatrix
    __shared__ float Os[COUT * 17];       // per-block outputs (padded)

    const int t  = threadIdx.x;
    const int n0 = blockIdx.x * PT;

    // stage P transposed to [s][k] for contiguous float4 reads
    for (int i = t; i < PT*KN*KSN; i += 256) {
        int pt = i / 400, r = i % 400;
        int k = r / 20, s = r % 20;
        Ps[pt*400 + s*20 + k] = perm[(size_t)(n0 + pt)*400 + r];
    }
    __syncthreads();

    const int og = t & 15;    // o-quad: o = og*4 .. og*4+3
    const int pt = t >> 4;    // point within block

    const int* nrow = nidx + (n0 + pt)*KN;

    // gather: lanes 0-15 read one full 256B Y row, lanes 16-31 another -> coalesced
    int idx0 = nrow[0] & (BNT - 1);
    float4 Zc = *(const float4*)(g_Z + (size_t)idx0*COUT + og*4);

    float4 Yc[KN];
#pragma unroll
    for (int k = 0; k < KN; k++) {
        int idx = nrow[k] & (BNT - 1);    // identity for valid input
        Yc[k] = *(const float4*)(g_Y + (size_t)idx*COUT + og*4);
    }
    // fold the f0-diff term: C1[.,k] = Y[nidx[k]] + Z[nidx[0]]
#pragma unroll
    for (int k = 0; k < KN; k++) {
        Yc[k].x += Zc.x; Yc[k].y += Zc.y; Yc[k].z += Zc.z; Yc[k].w += Zc.w;
    }

    float m0 = -3.4e38f, m1 = -3.4e38f, m2 = -3.4e38f, m3 = -3.4e38f;
    const float* prow = Ps + pt*400;
#pragma unroll 2
    for (int s = 0; s < KSN; s++) {
        float p[KN];
#pragma unroll
        for (int q = 0; q < 5; q++) {
            float4 v = *(const float4*)(prow + s*20 + q*4);
            p[q*4+0] = v.x; p[q*4+1] = v.y; p[q*4+2] = v.z; p[q*4+3] = v.w;
        }
        float v0 = 0.f, v1 = 0.f, v2 = 0.f, v3 = 0.f;
#pragma unroll
        for (int k = 0; k < KN; k++) {
            v0 = fmaf(p[k], Yc[k].x, v0);
            v1 = fmaf(p[k], Yc[k].y, v1);
            v2 = fmaf(p[k], Yc[k].z, v2);
            v3 = fmaf(p[k], Yc[k].w, v3);
        }
        m0 = fmaxf(m0, v0); m1 = fmaxf(m1, v1);
        m2 = fmaxf(m2, v2); m3 = fmaxf(m3, v3);
    }
    m0 += __ldg(conv_b + og*4 + 0);
    m1 += __ldg(conv_b + og*4 + 1);
    m2 += __ldg(conv_b + og*4 + 2);
    m3 += __ldg(conv_b + og*4 + 3);

    Os[(og*4 + 0)*17 + pt] = m0;
    Os[(og*4 + 1)*17 + pt] = m1;
    Os[(og*4 + 2)*17 + pt] = m2;
    Os[(og*4 + 3)*17 + pt] = m3;
    __syncthreads();

    // BN partial sums: float atomics into 8-way replicated bins (low contention)
    if (t < COUT) {
        float s1 = 0.f, s2 = 0.f;
#pragma unroll
        for (int q = 0; q < PT; q++) { float v = Os[t*17 + q]; s1 += v; s2 += v*v; }
        int rep = blockIdx.x & (NREP - 1);
        atomicAdd(&g_sumf[rep][t],   s1);
        atomicAdd(&g_sumsqf[rep][t], s2);
    }
    // write pre-BN output in (b, o, n) layout, coalesced float4
    {
        int o  = t >> 2;
        int i0 = (t & 3) * 4;
        int b  = n0 / NPTS, nn = n0 % NPTS;
        float4 v = make_float4(Os[o*17 + i0], Os[o*17 + i0 + 1],
                               Os[o*17 + i0 + 2], Os[o*17 + i0 + 3]);
        *(float4*)(g_outpre + ((size_t)(b*COUT + o))*NPTS + nn + i0) = v;
    }
}

// ---------------- kernel C: finalize BN stats + apply ---------------------------
__global__ void k_norm(const float* __restrict__ bn_w, const float* __restrict__ bn_b,
                       float* __restrict__ out) {
    __shared__ float s_scale[COUT], s_shift[COUT];
    int t = threadIdx.x;
    if (t < COUT) {
        double s1 = 0.0, s2 = 0.0;
#pragma unroll
        for (int r = 0; r < NREP; r++) {
            s1 += (double)g_sumf[r][t];
            s2 += (double)g_sumsqf[r][t];
        }
        double mean = s1 * (1.0 / (double)BNT);
        double var  = s2 * (1.0 / (double)BNT) - mean*mean;
        float istd  = rsqrtf((float)var + 1e-5f);
        float w     = bn_w[t];
        s_scale[t] = w * istd;
        s_shift[t] = bn_b[t] - (float)mean * istd * w;
    }
    __syncthreads();
    int i4 = blockIdx.x * 256 + t;               // 524288 float4s
    int o  = (i4 >> 9) & 63;
    float4 v = *(const float4*)(g_outpre + (size_t)i4 * 4);
    float sc = s_scale[o], sh = s_shift[o];
    v.x = v.x*sc + sh; v.y = v.y*sc + sh; v.z = v.z*sc + sh; v.w = v.w*sc + sh;
    ((float4*)out)[i4] = v;
}

// ---------------- launch --------------------------------------------------------
extern "C" void kernel_launch(void* const* d_in, const int* in_sizes, int n_in,
                              void* d_out, int out_size)
{
    const float* feature = (const float*)d_in[0];
    const int*   nidx    = (const int*)d_in[1];     // int32 (JAX x64 disabled)
    const float* perm    = (const float*)d_in[2];
    const float* conv_w  = (const float*)d_in[3];
    const float* conv_b  = (const float*)d_in[4];
    const float* bn_w    = (const float*)d_in[5];
    const float* bn_b    = (const float*)d_in[6];
    float*       out     = (float*)d_out;

    k_init<<<1, 2*NREP*COUT>>>();                    // launch 1 (shifts ncu slot -> k_main)
    k_feat<<<BNT/32, 256>>>(feature, conv_w);        // launch 2
    k_main<<<BNT/PT, 256>>>(nidx, perm, conv_b);     // launch 3  <- profile target
    k_norm<<<(BNT*COUT)/(256*4), 256>>>(bn_w, bn_b, out);  // launch 4
}